// round 11
// baseline (speedup 1.0000x reference)
#include <cuda_runtime.h>
#include <cuda_fp16.h>

#define HDIM   256
#define TPB    512
#define SB     264        // h row stride (fp16 elems)
#define TPAD   264        // c2 table row stride (f32)
#define XSTR   10         // xbuf lane stride (floats)
#define LN_EPS 1e-5f

// gamma-folded W_update in mma B-fragment lane order, fp16, uint4-packed:
// index (kt*16 + ntp)*32 + lane -> {nt0.r0, nt0.r1, nt1.r0, nt1.r1}
__device__ uint4 gBh[16 * 16 * 32];
// c-tables: rows 0..9 = c2[d] = emb(d)@W ; row 10 = c1 = gamma@W ; row 11 = c3 = beta@W + b_up
__device__ float gCtab[12 * 256];

__device__ __forceinline__ unsigned packh(float a, float b) {
    __half2 t = __floats2half2_rn(a, b);
    return *reinterpret_cast<unsigned*>(&t);
}
__device__ __forceinline__ float hfr(float v) {
    return __half2float(__float2half_rn(v));
}
// XLA-style rational tanh: 1 MUFU (rcp) + FFMA chain, ~1e-7 err, valid after clamp.
__device__ __forceinline__ float tanh_poly(float x) {
    x = fminf(fmaxf(x, -7.90531f), 7.90531f);
    float x2 = x * x;
    float p = fmaf(x2, -2.76076847742355e-16f, 2.00018790482477e-13f);
    p = fmaf(p, x2, -8.60467152213735e-11f);
    p = fmaf(p, x2,  5.12229709037114e-08f);
    p = fmaf(p, x2,  1.48572235717979e-05f);
    p = fmaf(p, x2,  6.37261928875436e-04f);
    p = fmaf(p, x2,  4.89352455891786e-03f);
    float q = fmaf(x2, 1.19825839466702e-06f, 1.18534705686654e-04f);
    q = fmaf(q, x2, 2.26843463243900e-03f);
    q = fmaf(q, x2, 4.89352518554385e-03f);
    return __fdividef(x * p, q);
}
__device__ __forceinline__ unsigned smem_u32(const void* p) {
    unsigned r;
    asm("{ .reg .u64 t; cvta.to.shared.u64 t, %1; cvt.u32.u64 %0, t; }" : "=r"(r) : "l"(p));
    return r;
}
__device__ __forceinline__ void ldmatrix_x4(unsigned a[4], unsigned addr) {
    asm volatile("ldmatrix.sync.aligned.m8n8.x4.shared.b16 {%0,%1,%2,%3}, [%4];"
                 : "=r"(a[0]), "=r"(a[1]), "=r"(a[2]), "=r"(a[3]) : "r"(addr));
}
__device__ __forceinline__ void mma_f16(float c[4], const unsigned a[4],
                                        unsigned b0, unsigned b1) {
    asm volatile("mma.sync.aligned.m16n8k16.row.col.f32.f16.f16.f32 "
                 "{%0,%1,%2,%3}, {%4,%5,%6,%7}, {%8,%9}, {%0,%1,%2,%3};"
                 : "+f"(c[0]), "+f"(c[1]), "+f"(c[2]), "+f"(c[3])
                 : "r"(a[0]), "r"(a[1]), "r"(a[2]), "r"(a[3]), "r"(b0), "r"(b1));
}

// ---------- prep 1: gamma-folded W -> fp16 uint4 fragment order ----------
__global__ void prep_w(const float* __restrict__ W, const float* __restrict__ gamma) {
    int idx = blockIdx.x * 256 + threadIdx.x;            // (kt, ntp, l): 16*16*32
    if (idx >= 16 * 16 * 32) return;
    int kt  = idx >> 9;
    int ntp = (idx >> 5) & 15;
    int l   = idx & 31;

    unsigned hi[4];
    #pragma unroll
    for (int s = 0; s < 2; s++) {
        int nt = 2 * ntp + s;
        int n  = nt * 8 + (l >> 2);
        int k0 = kt * 16 + (l & 3) * 2;
        hi[s * 2 + 0] = packh(W[(k0 + 0) * HDIM + n] * gamma[k0 + 0],
                              W[(k0 + 1) * HDIM + n] * gamma[k0 + 1]);
        hi[s * 2 + 1] = packh(W[(k0 + 8) * HDIM + n] * gamma[k0 + 8],
                              W[(k0 + 9) * HDIM + n] * gamma[k0 + 9]);
    }
    gBh[(kt * 16 + ntp) * 32 + l] = make_uint4(hi[0], hi[1], hi[2], hi[3]);
}

// ---------- prep 2: c-tables (12 GEMVs over W, fp32) ----------
__global__ void prep_c(const float* __restrict__ W,
                       const float* __restrict__ W_embed,
                       const float* __restrict__ b_embed,
                       const float* __restrict__ b_up,
                       const float* __restrict__ gamma,
                       const float* __restrict__ beta) {
    __shared__ float e[10][256];
    __shared__ float gsh[256], btsh[256];
    int n = threadIdx.x;
    #pragma unroll
    for (int d = 0; d < 10; d++)
        e[d][n] = tanh_poly((float)d * W_embed[n] + b_embed[n]);
    gsh[n]  = gamma[n];
    btsh[n] = beta[n];
    __syncthreads();

    float acc[12];
    #pragma unroll
    for (int i = 0; i < 12; i++) acc[i] = 0.f;
    for (int k = 0; k < 256; k++) {
        float wv = W[k * 256 + n];                       // coalesced
        #pragma unroll
        for (int d = 0; d < 10; d++) acc[d] = fmaf(e[d][k], wv, acc[d]);
        acc[10] = fmaf(gsh[k],  wv, acc[10]);
        acc[11] = fmaf(btsh[k], wv, acc[11]);
    }
    acc[11] += b_up[n];
    #pragma unroll
    for (int i = 0; i < 12; i++) gCtab[i * 256 + n] = acc[i];
}

// ---------- main persistent scan: 1 block = 16 batch rows ----------
__global__ void __launch_bounds__(TPB, 1)
rnn_scan_kernel(const float* __restrict__ x,        // [B, T, 1]
                const float* __restrict__ b_up,     // [H]
                const float* __restrict__ gamma,    // [H]
                const float* __restrict__ beta,     // [H]
                const float* __restrict__ W_out,    // [H, 10]
                const float* __restrict__ b_out,    // [10]
                float* __restrict__ out,            // [B, 10]
                int B, int T)
{
    extern __shared__ unsigned char smem_raw[];
    float* c2S  = (float*)smem_raw;                       // [10][TPAD]
    float* c1S  = c2S + 10 * TPAD;                        // [256]
    float* c3S  = c1S + 256;                              // [256]
    float* buS  = c3S + 256;                              // [256]
    float* gS   = buS + 256;                              // [256]
    float* btS  = gS + 256;                               // [256]
    float* xbuf = btS + 256;                              // [2][8][32][XSTR]
    float* pSum = xbuf + 2 * 8 * 32 * XSTR;               // [16][8]
    float* pSq  = pSum + 128;
    unsigned short* sHi = (unsigned short*)(pSq + 128);   // [16][SB] fp16 h_hi
    unsigned short* sLo = sHi + 16 * SB;                  // [16][SB] fp16 h_lo
    unsigned char*  xiT = (unsigned char*)(sLo + 16 * SB);// [T][16]

    const int tid = threadIdx.x;
    const int w   = tid >> 5;
    const int l   = tid & 31;
    const int wc  = w & 7;                                // cols [32wc, 32wc+32)
    const int kh  = w >> 3;                               // k half
    const int b0  = blockIdx.x * 16;

    unsigned* sHiU = (unsigned*)sHi;
    unsigned* sLoU = (unsigned*)sLo;

    const uint4* hiP0 = gBh + ((kh * 8) * 16 + 2 * wc) * 32 + l;
    const uint4* hiP1 = hiP0 + 32;

    // ---- one-time tables ----
    for (int idx = tid; idx < 10 * HDIM; idx += TPB) {
        int d  = idx / HDIM;
        int hh = idx - d * HDIM;
        c2S[d * TPAD + hh] = gCtab[d * 256 + hh];
    }
    for (int idx = tid; idx < HDIM; idx += TPB) {
        c1S[idx] = gCtab[10 * 256 + idx];
        c3S[idx] = gCtab[11 * 256 + idx];
        buS[idx] = b_up[idx];
        gS[idx]  = gamma[idx];
        btS[idx] = beta[idx];
    }
    for (int idx = tid; idx < 16 * T; idx += TPB) {
        int t = idx >> 4, m = idx & 15;
        xiT[t * 16 + m] = (unsigned char)__float2int_rn(x[(size_t)(b0 + m) * T + t]);
    }
    // zero-init h (so t=0 GEMM gives exactly P=0)
    for (int idx = tid; idx < 16 * 132; idx += TPB) {     // 132 u32 per row
        sHiU[idx] = 0u;
        sLoU[idx] = 0u;
    }
    __syncthreads();

    const int rr = (l >> 2) + kh * 8;                     // lane's row after exchange

    const int rowA  = (l & 7) + 8 * ((l >> 3) & 1);
    const int colbA = 8 * (l >> 4);
    const unsigned aHiBase = smem_u32(sHi) + (unsigned)(rowA * SB + colbA) * 2u
                           + (unsigned)(kh * 8) * 32u;
    const unsigned aLoBase = smem_u32(sLo) + (unsigned)(rowA * SB + colbA) * 2u
                           + (unsigned)(kh * 8) * 32u;

    float* xA = xbuf;                                     // kh1 -> kh0 (rows 0-7)
    float* xB = xbuf + 8 * 32 * XSTR;                     // kh0 -> kh1 (rows 8-15)
    float* xMineW = (kh ? xA : xB) + (wc * 32 + l) * XSTR;
    float* xMineR = (kh ? xB : xA) + (wc * 32 + l) * XSTR;

    for (int t = 0; t < T; t++) {
        // ---- stats of h(t-1): finalized here, hidden under the k-loop ----
        float mu = 0.f, rs = 0.f;
        if (t) {
            float4 s0 = *(const float4*)(pSum + rr * 8);
            float4 s1 = *(const float4*)(pSum + rr * 8 + 4);
            float4 q0 = *(const float4*)(pSq  + rr * 8);
            float4 q1 = *(const float4*)(pSq  + rr * 8 + 4);
            float sm = s0.x + s0.y + s0.z + s0.w + s1.x + s1.y + s1.z + s1.w;
            float qq = q0.x + q0.y + q0.z + q0.w + q1.x + q1.y + q1.z + q1.w;
            mu = sm * (1.0f / HDIM);
            rs = rsqrtf(qq * (1.0f / HDIM) - mu * mu + LN_EPS);
        }
        const float nrm = -rs * mu;
        const float* cxS = t ? c3S : buS;

        // ---------------- GEMM: P_partial = h(t-1) @ (gamma.W) over this k-half ----
        float acc[4][4];
        #pragma unroll
        for (int i = 0; i < 4; i++)
            #pragma unroll
            for (int p = 0; p < 4; p++) acc[i][p] = 0.f;

        uint4 h0[2], h1[2];
        unsigned aH[2][4], aL[2][4];
        h0[0] = __ldg(hiP0);
        h1[0] = __ldg(hiP1);
        ldmatrix_x4(aH[0], aHiBase);
        ldmatrix_x4(aL[0], aLoBase);

        #pragma unroll
        for (int kk = 0; kk < 8; kk++) {
            const int cur = kk & 1, nxt = cur ^ 1;
            if (kk < 7) {
                h0[nxt] = __ldg(hiP0 + (kk + 1) * 512);
                h1[nxt] = __ldg(hiP1 + (kk + 1) * 512);
                ldmatrix_x4(aH[nxt], aHiBase + (unsigned)(kk + 1) * 32u);
                ldmatrix_x4(aL[nxt], aLoBase + (unsigned)(kk + 1) * 32u);
            }
            mma_f16(acc[0], aH[cur], h0[cur].x, h0[cur].y);   // h_hi * W
            mma_f16(acc[1], aH[cur], h0[cur].z, h0[cur].w);
            mma_f16(acc[2], aH[cur], h1[cur].x, h1[cur].y);
            mma_f16(acc[3], aH[cur], h1[cur].z, h1[cur].w);
            mma_f16(acc[0], aL[cur], h0[cur].x, h0[cur].y);   // h_lo * W
            mma_f16(acc[1], aL[cur], h0[cur].z, h0[cur].w);
            mma_f16(acc[2], aL[cur], h1[cur].x, h1[cur].y);
            mma_f16(acc[3], aL[cur], h1[cur].z, h1[cur].w);
        }

        // ---- row-split K exchange: kh0 keeps rows 0-7, kh1 rows 8-15 ----
        #pragma unroll
        for (int nti = 0; nti < 4; nti++) {
            float2 snd = kh ? make_float2(acc[nti][0], acc[nti][1])
                            : make_float2(acc[nti][2], acc[nti][3]);
            *(float2*)(xMineW + nti * 2) = snd;
        }
        __syncthreads();                                   // bar1

        // ---- apply LN-as-postscale + embed + bias, tanh, store h, LN partials ----
        const int dd = (int)xiT[t * 16 + rr];
        float sum = 0.f, sq = 0.f;
        #pragma unroll
        for (int nti = 0; nti < 4; nti++) {
            float2 o = *(const float2*)(xMineR + nti * 2);
            float P0 = (kh ? acc[nti][2] : acc[nti][0]) + o.x;
            float P1 = (kh ? acc[nti][3] : acc[nti][1]) + o.y;

            int c0 = 32 * wc + 8 * nti + 2 * (l & 3);
            float2 c1v = *(const float2*)(c1S + c0);
            float2 c2v = *(const float2*)(c2S + dd * TPAD + c0);
            float2 cxv = *(const float2*)(cxS + c0);

            float v0 = fmaf(rs, P0, fmaf(nrm, c1v.x, c2v.x + cxv.x));
            float v1 = fmaf(rs, P1, fmaf(nrm, c1v.y, c2v.y + cxv.y));
            float hv0 = tanh_poly(v0);
            float hv1 = tanh_poly(v1);

            sum += hv0 + hv1;
            sq  += hv0 * hv0 + hv1 * hv1;

            float hh0 = hfr(hv0), hh1 = hfr(hv1);
            sHiU[rr * 132 + (c0 >> 1)] = packh(hh0, hh1);
            sLoU[rr * 132 + (c0 >> 1)] = packh(hv0 - hh0, hv1 - hh1);
        }
        // quad-reduce LN partials (32 cols per (row, wc))
        sum += __shfl_xor_sync(0xffffffffu, sum, 1);
        sum += __shfl_xor_sync(0xffffffffu, sum, 2);
        sq  += __shfl_xor_sync(0xffffffffu, sq, 1);
        sq  += __shfl_xor_sync(0xffffffffu, sq, 2);
        if ((l & 3) == 0) { pSum[rr * 8 + wc] = sum; pSq[rr * 8 + wc] = sq; }

        __syncthreads();                                   // bar2
    }

    // ---- output head: h_ln = (h - mu)*rs*gamma + beta, then @W_out + b_out ----
    if (tid < 160) {
        int m  = tid / 10;
        int cx = tid - m * 10;
        float4 s0 = *(const float4*)(pSum + m * 8);
        float4 s1 = *(const float4*)(pSum + m * 8 + 4);
        float4 q0 = *(const float4*)(pSq  + m * 8);
        float4 q1 = *(const float4*)(pSq  + m * 8 + 4);
        float sm = s0.x + s0.y + s0.z + s0.w + s1.x + s1.y + s1.z + s1.w;
        float qq = q0.x + q0.y + q0.z + q0.w + q1.x + q1.y + q1.z + q1.w;
        float mu = sm * (1.0f / HDIM);
        float rs = rsqrtf(qq * (1.0f / HDIM) - mu * mu + LN_EPS);

        const __half* rh = (const __half*)sHi + m * SB;
        const __half* rl = (const __half*)sLo + m * SB;
        float a = b_out[cx];
        #pragma unroll 8
        for (int k = 0; k < HDIM; k++) {
            float h  = __half2float(rh[k]) + __half2float(rl[k]);
            float hl = (h - mu) * rs * gS[k] + btS[k];
            a = fmaf(hl, __ldg(W_out + k * 10 + cx), a);
        }
        out[(size_t)(b0 + m) * 10 + cx] = a;
    }
}

extern "C" void kernel_launch(void* const* d_in, const int* in_sizes, int n_in,
                              void* d_out, int out_size)
{
    const float* x       = (const float*)d_in[0];
    const float* W_embed = (const float*)d_in[1];
    const float* b_embed = (const float*)d_in[2];
    const float* W_up    = (const float*)d_in[3];
    const float* b_up    = (const float*)d_in[4];
    const float* gamma   = (const float*)d_in[5];
    const float* beta    = (const float*)d_in[6];
    const float* W_out   = (const float*)d_in[7];
    const float* b_out   = (const float*)d_in[8];
    float* out = (float*)d_out;

    int B = out_size / 10;          // 2048
    int T = in_sizes[0] / B;        // 512

    prep_w<<<32, 256>>>(W_up, gamma);
    prep_c<<<1, 256>>>(W_up, W_embed, b_embed, b_up, gamma, beta);

    size_t smem = (size_t)10 * TPAD * 4          // c2S
                + 5 * 256 * 4                    // c1,c3,bu,g,bt
                + (size_t)2 * 8 * 32 * XSTR * 4  // xbuf
                + 2 * 128 * 4                    // pSum/pSq
                + (size_t)2 * 16 * SB * 2        // sHi/sLo
                + (size_t)16 * T                 // xiT
                + 64;
    cudaFuncSetAttribute(rnn_scan_kernel,
                         cudaFuncAttributeMaxDynamicSharedMemorySize, (int)smem);
    rnn_scan_kernel<<<B / 16, TPB, smem>>>(x, b_up, gamma, beta,
                                           W_out, b_out, out, B, T);
}

// round 12
// speedup vs baseline: 2.0681x; 2.0681x over previous
#include <cuda_runtime.h>
#include <cuda_fp16.h>

#define HDIM   256
#define TPB    512
#define SB     264        // h row stride (fp16 elems)
#define TPAD   264        // c2 table row stride (f32)
#define XSTR   10         // xbuf lane stride (floats)
#define LN_EPS 1e-5f

// gamma-folded W_update in mma B-fragment lane order, fp16, uint4-packed:
// index (kt*16 + ntp)*32 + lane -> {nt0.r0, nt0.r1, nt1.r0, nt1.r1}
__device__ uint4 gBh[16 * 16 * 32];
// c-tables: rows 0..9 = c2[d] = emb(d)@W ; row 10 = c1 = gamma@W ; row 11 = c3 = beta@W + b_up
__device__ float gCtab[12 * 256];

__device__ __forceinline__ unsigned packh(float a, float b) {
    __half2 t = __floats2half2_rn(a, b);
    return *reinterpret_cast<unsigned*>(&t);
}
__device__ __forceinline__ float hfr(float v) {
    return __half2float(__float2half_rn(v));
}
// Accurate fast tanh (~1e-6 rel err, 2 MUFU); validated R10 at full speed.
__device__ __forceinline__ float tanh_fast(float v) {
    float e = __expf(2.0f * v);
    return 1.0f - __fdividef(2.0f, e + 1.0f);
}
__device__ __forceinline__ unsigned smem_u32(const void* p) {
    unsigned r;
    asm("{ .reg .u64 t; cvta.to.shared.u64 t, %1; cvt.u32.u64 %0, t; }" : "=r"(r) : "l"(p));
    return r;
}
__device__ __forceinline__ void ldmatrix_x4(unsigned a[4], unsigned addr) {
    asm volatile("ldmatrix.sync.aligned.m8n8.x4.shared.b16 {%0,%1,%2,%3}, [%4];"
                 : "=r"(a[0]), "=r"(a[1]), "=r"(a[2]), "=r"(a[3]) : "r"(addr));
}
__device__ __forceinline__ void mma_f16(float c[4], const unsigned a[4],
                                        unsigned b0, unsigned b1) {
    asm volatile("mma.sync.aligned.m16n8k16.row.col.f32.f16.f16.f32 "
                 "{%0,%1,%2,%3}, {%4,%5,%6,%7}, {%8,%9}, {%0,%1,%2,%3};"
                 : "+f"(c[0]), "+f"(c[1]), "+f"(c[2]), "+f"(c[3])
                 : "r"(a[0]), "r"(a[1]), "r"(a[2]), "r"(a[3]), "r"(b0), "r"(b1));
}

// ---------- single prep launch: blocks 0-31 pack W, block 32 builds c-tables ----------
__global__ void prep_all(const float* __restrict__ W,
                         const float* __restrict__ gamma,
                         const float* __restrict__ W_embed,
                         const float* __restrict__ b_embed,
                         const float* __restrict__ b_up,
                         const float* __restrict__ beta) {
    if (blockIdx.x < 32) {
        int idx = blockIdx.x * 256 + threadIdx.x;        // (kt, ntp, l): 16*16*32
        int kt  = idx >> 9;
        int ntp = (idx >> 5) & 15;
        int l   = idx & 31;
        unsigned hi[4];
        #pragma unroll
        for (int s = 0; s < 2; s++) {
            int nt = 2 * ntp + s;
            int n  = nt * 8 + (l >> 2);
            int k0 = kt * 16 + (l & 3) * 2;
            hi[s * 2 + 0] = packh(W[(k0 + 0) * HDIM + n] * gamma[k0 + 0],
                                  W[(k0 + 1) * HDIM + n] * gamma[k0 + 1]);
            hi[s * 2 + 1] = packh(W[(k0 + 8) * HDIM + n] * gamma[k0 + 8],
                                  W[(k0 + 9) * HDIM + n] * gamma[k0 + 9]);
        }
        gBh[(kt * 16 + ntp) * 32 + l] = make_uint4(hi[0], hi[1], hi[2], hi[3]);
    } else {
        __shared__ float e[10][256];
        __shared__ float gsh[256], btsh[256];
        int n = threadIdx.x;
        #pragma unroll
        for (int d = 0; d < 10; d++)
            e[d][n] = tanhf((float)d * W_embed[n] + b_embed[n]);
        gsh[n]  = gamma[n];
        btsh[n] = beta[n];
        __syncthreads();

        float acc[12];
        #pragma unroll
        for (int i = 0; i < 12; i++) acc[i] = 0.f;
        #pragma unroll 4
        for (int k = 0; k < 256; k++) {
            float wv = W[k * 256 + n];                   // coalesced
            #pragma unroll
            for (int d = 0; d < 10; d++) acc[d] = fmaf(e[d][k], wv, acc[d]);
            acc[10] = fmaf(gsh[k],  wv, acc[10]);
            acc[11] = fmaf(btsh[k], wv, acc[11]);
        }
        acc[11] += b_up[n];
        #pragma unroll
        for (int i = 0; i < 12; i++) gCtab[i * 256 + n] = acc[i];
    }
}

// ---------- main persistent scan: 1 block = 16 batch rows ----------
__global__ void __launch_bounds__(TPB, 1)
rnn_scan_kernel(const float* __restrict__ x,        // [B, T, 1]
                const float* __restrict__ b_up,     // [H]
                const float* __restrict__ gamma,    // [H]
                const float* __restrict__ beta,     // [H]
                const float* __restrict__ W_out,    // [H, 10]
                const float* __restrict__ b_out,    // [10]
                float* __restrict__ out,            // [B, 10]
                int B, int T)
{
    extern __shared__ unsigned char smem_raw[];
    float* c2S  = (float*)smem_raw;                       // [10][TPAD]
    float* c1S  = c2S + 10 * TPAD;                        // [256]
    float* c3S  = c1S + 256;                              // [256]
    float* buS  = c3S + 256;                              // [256]
    float* gS   = buS + 256;                              // [256]
    float* btS  = gS + 256;                               // [256]
    float* xbuf = btS + 256;                              // [2][8][32][XSTR]
    float* pSum = xbuf + 2 * 8 * 32 * XSTR;               // [16][8]
    float* pSq  = pSum + 128;
    unsigned short* sHi = (unsigned short*)(pSq + 128);   // [16][SB] fp16 h_hi
    unsigned short* sLo = sHi + 16 * SB;                  // [16][SB] fp16 h_lo
    unsigned char*  xiT = (unsigned char*)(sLo + 16 * SB);// [T][16]

    const int tid = threadIdx.x;
    const int w   = tid >> 5;
    const int l   = tid & 31;
    const int wc  = w & 7;                                // cols [32wc, 32wc+32)
    const int kh  = w >> 3;                               // k half
    const int b0  = blockIdx.x * 16;

    unsigned* sHiU = (unsigned*)sHi;
    unsigned* sLoU = (unsigned*)sLo;

    const uint4* hiP0 = gBh + ((kh * 8) * 16 + 2 * wc) * 32 + l;
    const uint4* hiP1 = hiP0 + 32;

    // ---- one-time tables ----
    for (int idx = tid; idx < 10 * HDIM; idx += TPB) {
        int d  = idx / HDIM;
        int hh = idx - d * HDIM;
        c2S[d * TPAD + hh] = gCtab[d * 256 + hh];
    }
    for (int idx = tid; idx < HDIM; idx += TPB) {
        c1S[idx] = gCtab[10 * 256 + idx];
        c3S[idx] = gCtab[11 * 256 + idx];
        buS[idx] = b_up[idx];
        gS[idx]  = gamma[idx];
        btS[idx] = beta[idx];
    }
    for (int idx = tid; idx < 16 * T; idx += TPB) {
        int t = idx >> 4, m = idx & 15;
        xiT[t * 16 + m] = (unsigned char)__float2int_rn(x[(size_t)(b0 + m) * T + t]);
    }
    // zero-init h (t=0 GEMM then yields exactly P=0)
    for (int idx = tid; idx < 16 * 132; idx += TPB) {
        sHiU[idx] = 0u;
        sLoU[idx] = 0u;
    }
    __syncthreads();

    const int rr = (l >> 2) + kh * 8;                     // lane's row after exchange

    const int rowA  = (l & 7) + 8 * ((l >> 3) & 1);
    const int colbA = 8 * (l >> 4);
    const unsigned aHiBase = smem_u32(sHi) + (unsigned)(rowA * SB + colbA) * 2u
                           + (unsigned)(kh * 8) * 32u;
    const unsigned aLoBase = smem_u32(sLo) + (unsigned)(rowA * SB + colbA) * 2u
                           + (unsigned)(kh * 8) * 32u;

    float* xA = xbuf;                                     // kh1 -> kh0 (rows 0-7)
    float* xB = xbuf + 8 * 32 * XSTR;                     // kh0 -> kh1 (rows 8-15)
    float* xMineW = (kh ? xA : xB) + (wc * 32 + l) * XSTR;
    float* xMineR = (kh ? xB : xA) + (wc * 32 + l) * XSTR;

    for (int t = 0; t < T; t++) {
        // ---------------- GEMM: P_partial = h(t-1) @ (gamma.W) over this k-half ----
        float acc[4][4];
        #pragma unroll
        for (int i = 0; i < 4; i++)
            #pragma unroll
            for (int p = 0; p < 4; p++) acc[i][p] = 0.f;

        uint4 h0[2], h1[2];
        unsigned aH[2][4], aL[2][4];
        h0[0] = __ldg(hiP0);
        h1[0] = __ldg(hiP1);
        ldmatrix_x4(aH[0], aHiBase);
        ldmatrix_x4(aL[0], aLoBase);

        #pragma unroll
        for (int kk = 0; kk < 8; kk++) {
            const int cur = kk & 1, nxt = cur ^ 1;
            if (kk < 7) {
                h0[nxt] = __ldg(hiP0 + (kk + 1) * 512);
                h1[nxt] = __ldg(hiP1 + (kk + 1) * 512);
                ldmatrix_x4(aH[nxt], aHiBase + (unsigned)(kk + 1) * 32u);
                ldmatrix_x4(aL[nxt], aLoBase + (unsigned)(kk + 1) * 32u);
            }
            mma_f16(acc[0], aH[cur], h0[cur].x, h0[cur].y);   // h_hi * W
            mma_f16(acc[1], aH[cur], h0[cur].z, h0[cur].w);
            mma_f16(acc[2], aH[cur], h1[cur].x, h1[cur].y);
            mma_f16(acc[3], aH[cur], h1[cur].z, h1[cur].w);
            mma_f16(acc[0], aL[cur], h0[cur].x, h0[cur].y);   // h_lo * W
            mma_f16(acc[1], aL[cur], h0[cur].z, h0[cur].w);
            mma_f16(acc[2], aL[cur], h1[cur].x, h1[cur].y);
            mma_f16(acc[3], aL[cur], h1[cur].z, h1[cur].w);
        }

        // ---- row-split K exchange: kh0 keeps rows 0-7, kh1 rows 8-15 ----
        #pragma unroll
        for (int nti = 0; nti < 4; nti++) {
            float2 snd = kh ? make_float2(acc[nti][0], acc[nti][1])
                            : make_float2(acc[nti][2], acc[nti][3]);
            *(float2*)(xMineW + nti * 2) = snd;
        }
        __syncthreads();                                   // bar1

        // ---- epilogue: stats of h(t-1) (transient regs), LN-as-postscale, tanh ----
        float mu = 0.f, rs = 0.f;
        if (t) {
            float4 s0 = *(const float4*)(pSum + rr * 8);
            float4 s1 = *(const float4*)(pSum + rr * 8 + 4);
            float4 q0 = *(const float4*)(pSq  + rr * 8);
            float4 q1 = *(const float4*)(pSq  + rr * 8 + 4);
            float sm = s0.x + s0.y + s0.z + s0.w + s1.x + s1.y + s1.z + s1.w;
            float qq = q0.x + q0.y + q0.z + q0.w + q1.x + q1.y + q1.z + q1.w;
            mu = sm * (1.0f / HDIM);
            rs = rsqrtf(qq * (1.0f / HDIM) - mu * mu + LN_EPS);
        }
        const float nrm = -rs * mu;
        const float* cxS = t ? c3S : buS;
        const int dd = (int)xiT[t * 16 + rr];

        float sum = 0.f, sq = 0.f;
        #pragma unroll
        for (int nti = 0; nti < 4; nti++) {
            float2 o = *(const float2*)(xMineR + nti * 2);
            float P0 = (kh ? acc[nti][2] : acc[nti][0]) + o.x;
            float P1 = (kh ? acc[nti][3] : acc[nti][1]) + o.y;

            int c0 = 32 * wc + 8 * nti + 2 * (l & 3);
            float2 c1v = *(const float2*)(c1S + c0);
            float2 c2v = *(const float2*)(c2S + dd * TPAD + c0);
            float2 cxv = *(const float2*)(cxS + c0);

            float v0 = fmaf(rs, P0, fmaf(nrm, c1v.x, c2v.x + cxv.x));
            float v1 = fmaf(rs, P1, fmaf(nrm, c1v.y, c2v.y + cxv.y));
            float hv0 = tanh_fast(v0);
            float hv1 = tanh_fast(v1);

            sum += hv0 + hv1;
            sq  += hv0 * hv0 + hv1 * hv1;

            float hh0 = hfr(hv0), hh1 = hfr(hv1);
            sHiU[rr * 132 + (c0 >> 1)] = packh(hh0, hh1);
            sLoU[rr * 132 + (c0 >> 1)] = packh(hv0 - hh0, hv1 - hh1);
        }
        sum += __shfl_xor_sync(0xffffffffu, sum, 1);
        sum += __shfl_xor_sync(0xffffffffu, sum, 2);
        sq  += __shfl_xor_sync(0xffffffffu, sq, 1);
        sq  += __shfl_xor_sync(0xffffffffu, sq, 2);
        if ((l & 3) == 0) { pSum[rr * 8 + wc] = sum; pSq[rr * 8 + wc] = sq; }

        __syncthreads();                                   // bar2
    }

    // ---- output head: h_ln = (h - mu)*rs*gamma + beta, then @W_out + b_out ----
    if (tid < 160) {
        int m  = tid / 10;
        int cx = tid - m * 10;
        float4 s0 = *(const float4*)(pSum + m * 8);
        float4 s1 = *(const float4*)(pSum + m * 8 + 4);
        float4 q0 = *(const float4*)(pSq  + m * 8);
        float4 q1 = *(const float4*)(pSq  + m * 8 + 4);
        float sm = s0.x + s0.y + s0.z + s0.w + s1.x + s1.y + s1.z + s1.w;
        float qq = q0.x + q0.y + q0.z + q0.w + q1.x + q1.y + q1.z + q1.w;
        float mu = sm * (1.0f / HDIM);
        float rs = rsqrtf(qq * (1.0f / HDIM) - mu * mu + LN_EPS);

        const __half* rh = (const __half*)sHi + m * SB;
        const __half* rl = (const __half*)sLo + m * SB;
        float a = b_out[cx];
        #pragma unroll 8
        for (int k = 0; k < HDIM; k++) {
            float h  = __half2float(rh[k]) + __half2float(rl[k]);
            float hl = (h - mu) * rs * gS[k] + btS[k];
            a = fmaf(hl, __ldg(W_out + k * 10 + cx), a);
        }
        out[(size_t)(b0 + m) * 10 + cx] = a;
    }
}

extern "C" void kernel_launch(void* const* d_in, const int* in_sizes, int n_in,
                              void* d_out, int out_size)
{
    const float* x       = (const float*)d_in[0];
    const float* W_embed = (const float*)d_in[1];
    const float* b_embed = (const float*)d_in[2];
    const float* W_up    = (const float*)d_in[3];
    const float* b_up    = (const float*)d_in[4];
    const float* gamma   = (const float*)d_in[5];
    const float* beta    = (const float*)d_in[6];
    const float* W_out   = (const float*)d_in[7];
    const float* b_out   = (const float*)d_in[8];
    float* out = (float*)d_out;

    int B = out_size / 10;          // 2048
    int T = in_sizes[0] / B;        // 512

    prep_all<<<33, 256>>>(W_up, gamma, W_embed, b_embed, b_up, beta);

    size_t smem = (size_t)10 * TPAD * 4          // c2S
                + 5 * 256 * 4                    // c1,c3,bu,g,bt
                + (size_t)2 * 8 * 32 * XSTR * 4  // xbuf
                + 2 * 128 * 4                    // pSum/pSq
                + (size_t)2 * 16 * SB * 2        // sHi/sLo
                + (size_t)16 * T                 // xiT
                + 64;
    cudaFuncSetAttribute(rnn_scan_kernel,
                         cudaFuncAttributeMaxDynamicSharedMemorySize, (int)smem);
    rnn_scan_kernel<<<B / 16, TPB, smem>>>(x, b_up, gamma, beta,
                                           W_out, b_out, out, B, T);
}

// round 13
// speedup vs baseline: 2.9944x; 1.4479x over previous
#include <cuda_runtime.h>
#include <cuda_fp16.h>

#define HDIM   256
#define TPB    512
#define SB     264        // h row stride (fp16 elems)
#define TPAD   264        // c2 table row stride (f32)
#define XSTR   10         // xbuf lane stride (floats)
#define LN_EPS 1e-5f

// gamma-folded W_update in mma B-fragment lane order, fp16, uint4-packed:
// index (kt*16 + ntp)*32 + lane -> {nt0.r0, nt0.r1, nt1.r0, nt1.r1}
__device__ uint4 gBh[16 * 16 * 32];
// c-tables: rows 0..9 = c2[d] = emb(d)@W ; row 10 = c1 = gamma@W ; row 11 = c3 = beta@W + b_up
__device__ float gCtab[12 * 256];

__device__ __forceinline__ unsigned packh(float a, float b) {
    __half2 t = __floats2half2_rn(a, b);
    return *reinterpret_cast<unsigned*>(&t);
}
// Accurate fast tanh (~1e-6 rel err, 2 MUFU); validated R10/R12 at full speed.
__device__ __forceinline__ float tanh_fast(float v) {
    float e = __expf(2.0f * v);
    return 1.0f - __fdividef(2.0f, e + 1.0f);
}
__device__ __forceinline__ unsigned smem_u32(const void* p) {
    unsigned r;
    asm("{ .reg .u64 t; cvta.to.shared.u64 t, %1; cvt.u32.u64 %0, t; }" : "=r"(r) : "l"(p));
    return r;
}
__device__ __forceinline__ void ldmatrix_x4(unsigned a[4], unsigned addr) {
    asm volatile("ldmatrix.sync.aligned.m8n8.x4.shared.b16 {%0,%1,%2,%3}, [%4];"
                 : "=r"(a[0]), "=r"(a[1]), "=r"(a[2]), "=r"(a[3]) : "r"(addr));
}
__device__ __forceinline__ void mma_f16(float c[4], const unsigned a[4],
                                        unsigned b0, unsigned b1) {
    asm volatile("mma.sync.aligned.m16n8k16.row.col.f32.f16.f16.f32 "
                 "{%0,%1,%2,%3}, {%4,%5,%6,%7}, {%8,%9}, {%0,%1,%2,%3};"
                 : "+f"(c[0]), "+f"(c[1]), "+f"(c[2]), "+f"(c[3])
                 : "r"(a[0]), "r"(a[1]), "r"(a[2]), "r"(a[3]), "r"(b0), "r"(b1));
}

// ---------- single prep launch: blocks 0-31 pack W, block 32 builds c-tables ----------
__global__ void prep_all(const float* __restrict__ W,
                         const float* __restrict__ gamma,
                         const float* __restrict__ W_embed,
                         const float* __restrict__ b_embed,
                         const float* __restrict__ b_up,
                         const float* __restrict__ beta) {
    if (blockIdx.x < 32) {
        int idx = blockIdx.x * 256 + threadIdx.x;        // (kt, ntp, l): 16*16*32
        int kt  = idx >> 9;
        int ntp = (idx >> 5) & 15;
        int l   = idx & 31;
        unsigned hi[4];
        #pragma unroll
        for (int s = 0; s < 2; s++) {
            int nt = 2 * ntp + s;
            int n  = nt * 8 + (l >> 2);
            int k0 = kt * 16 + (l & 3) * 2;
            hi[s * 2 + 0] = packh(W[(k0 + 0) * HDIM + n] * gamma[k0 + 0],
                                  W[(k0 + 1) * HDIM + n] * gamma[k0 + 1]);
            hi[s * 2 + 1] = packh(W[(k0 + 8) * HDIM + n] * gamma[k0 + 8],
                                  W[(k0 + 9) * HDIM + n] * gamma[k0 + 9]);
        }
        gBh[(kt * 16 + ntp) * 32 + l] = make_uint4(hi[0], hi[1], hi[2], hi[3]);
    } else {
        __shared__ float e[10][256];
        __shared__ float gsh[256], btsh[256];
        int n = threadIdx.x;
        #pragma unroll
        for (int d = 0; d < 10; d++)
            e[d][n] = tanhf((float)d * W_embed[n] + b_embed[n]);
        gsh[n]  = gamma[n];
        btsh[n] = beta[n];
        __syncthreads();

        float acc[12];
        #pragma unroll
        for (int i = 0; i < 12; i++) acc[i] = 0.f;
        #pragma unroll 4
        for (int k = 0; k < 256; k++) {
            float wv = W[k * 256 + n];                   // coalesced
            #pragma unroll
            for (int d = 0; d < 10; d++) acc[d] = fmaf(e[d][k], wv, acc[d]);
            acc[10] = fmaf(gsh[k],  wv, acc[10]);
            acc[11] = fmaf(btsh[k], wv, acc[11]);
        }
        acc[11] += b_up[n];
        #pragma unroll
        for (int i = 0; i < 12; i++) gCtab[i * 256 + n] = acc[i];
    }
}

// ---------- main persistent scan: 1 block = 16 batch rows ----------
__global__ void __launch_bounds__(TPB, 1)
rnn_scan_kernel(const float* __restrict__ x,        // [B, T, 1]
                const float* __restrict__ b_up,     // [H]
                const float* __restrict__ gamma,    // [H]
                const float* __restrict__ beta,     // [H]
                const float* __restrict__ W_out,    // [H, 10]
                const float* __restrict__ b_out,    // [10]
                float* __restrict__ out,            // [B, 10]
                int B, int T)
{
    extern __shared__ unsigned char smem_raw[];
    float* c2S  = (float*)smem_raw;                       // [10][TPAD]
    float* c1S  = c2S + 10 * TPAD;                        // [256]
    float* c3S  = c1S + 256;                              // [256]
    float* buS  = c3S + 256;                              // [256]
    float* gS   = buS + 256;                              // [256]
    float* btS  = gS + 256;                               // [256]
    float* xbuf = btS + 256;                              // [2][8][32][XSTR]
    float* pSum = xbuf + 2 * 8 * 32 * XSTR;               // [16][8]
    float* pSq  = pSum + 128;
    unsigned short* sHi = (unsigned short*)(pSq + 128);   // [16][SB] fp16 h
    unsigned char*  xiT = (unsigned char*)(sHi + 16 * SB);// [T][16]

    const int tid = threadIdx.x;
    const int w   = tid >> 5;
    const int l   = tid & 31;
    const int wc  = w & 7;                                // cols [32wc, 32wc+32)
    const int kh  = w >> 3;                               // k half
    const int b0  = blockIdx.x * 16;

    unsigned* sHiU = (unsigned*)sHi;

    const uint4* hiP0 = gBh + ((kh * 8) * 16 + 2 * wc) * 32 + l;
    const uint4* hiP1 = hiP0 + 32;

    // ---- one-time tables ----
    for (int idx = tid; idx < 10 * HDIM; idx += TPB) {
        int d  = idx / HDIM;
        int hh = idx - d * HDIM;
        c2S[d * TPAD + hh] = gCtab[d * 256 + hh];
    }
    for (int idx = tid; idx < HDIM; idx += TPB) {
        c1S[idx] = gCtab[10 * 256 + idx];
        c3S[idx] = gCtab[11 * 256 + idx];
        buS[idx] = b_up[idx];
        gS[idx]  = gamma[idx];
        btS[idx] = beta[idx];
    }
    for (int idx = tid; idx < 16 * T; idx += TPB) {
        int t = idx >> 4, m = idx & 15;
        xiT[t * 16 + m] = (unsigned char)__float2int_rn(x[(size_t)(b0 + m) * T + t]);
    }
    // zero-init h (t=0 GEMM then yields exactly P=0)
    for (int idx = tid; idx < 16 * 132; idx += TPB) sHiU[idx] = 0u;
    __syncthreads();

    const int rr = (l >> 2) + kh * 8;                     // lane's row after exchange

    const int rowA  = (l & 7) + 8 * ((l >> 3) & 1);
    const int colbA = 8 * (l >> 4);
    const unsigned aHiBase = smem_u32(sHi) + (unsigned)(rowA * SB + colbA) * 2u
                           + (unsigned)(kh * 8) * 32u;

    float* xA = xbuf;                                     // kh1 -> kh0 (rows 0-7)
    float* xB = xbuf + 8 * 32 * XSTR;                     // kh0 -> kh1 (rows 8-15)
    float* xMineW = (kh ? xA : xB) + (wc * 32 + l) * XSTR;
    float* xMineR = (kh ? xB : xA) + (wc * 32 + l) * XSTR;

    for (int t = 0; t < T; t++) {
        // ---------------- GEMM: P_partial = h(t-1) @ (gamma.W) over this k-half ----
        float acc[4][4];
        #pragma unroll
        for (int i = 0; i < 4; i++)
            #pragma unroll
            for (int p = 0; p < 4; p++) acc[i][p] = 0.f;

        uint4 h0[2], h1[2];
        unsigned aH[2][4];
        h0[0] = __ldg(hiP0);
        h1[0] = __ldg(hiP1);
        ldmatrix_x4(aH[0], aHiBase);

        #pragma unroll
        for (int kk = 0; kk < 8; kk++) {
            const int cur = kk & 1, nxt = cur ^ 1;
            if (kk < 7) {
                h0[nxt] = __ldg(hiP0 + (kk + 1) * 512);
                h1[nxt] = __ldg(hiP1 + (kk + 1) * 512);
                ldmatrix_x4(aH[nxt], aHiBase + (unsigned)(kk + 1) * 32u);
            }
            mma_f16(acc[0], aH[cur], h0[cur].x, h0[cur].y);
            mma_f16(acc[1], aH[cur], h0[cur].z, h0[cur].w);
            mma_f16(acc[2], aH[cur], h1[cur].x, h1[cur].y);
            mma_f16(acc[3], aH[cur], h1[cur].z, h1[cur].w);
        }

        // ---- row-split K exchange: kh0 keeps rows 0-7, kh1 rows 8-15 ----
        #pragma unroll
        for (int nti = 0; nti < 4; nti++) {
            float2 snd = kh ? make_float2(acc[nti][0], acc[nti][1])
                            : make_float2(acc[nti][2], acc[nti][3]);
            *(float2*)(xMineW + nti * 2) = snd;
        }
        __syncthreads();                                   // bar1

        // ---- epilogue: stats of h(t-1) (transient regs), LN-as-postscale, tanh ----
        float mu = 0.f, rs = 0.f;
        if (t) {
            float4 s0 = *(const float4*)(pSum + rr * 8);
            float4 s1 = *(const float4*)(pSum + rr * 8 + 4);
            float4 q0 = *(const float4*)(pSq  + rr * 8);
            float4 q1 = *(const float4*)(pSq  + rr * 8 + 4);
            float sm = s0.x + s0.y + s0.z + s0.w + s1.x + s1.y + s1.z + s1.w;
            float qq = q0.x + q0.y + q0.z + q0.w + q1.x + q1.y + q1.z + q1.w;
            mu = sm * (1.0f / HDIM);
            rs = rsqrtf(qq * (1.0f / HDIM) - mu * mu + LN_EPS);
        }
        const float nrm = -rs * mu;
        const float* cxS = t ? c3S : buS;
        const int dd = (int)xiT[t * 16 + rr];

        float sum = 0.f, sq = 0.f;
        #pragma unroll
        for (int nti = 0; nti < 4; nti++) {
            float2 o = *(const float2*)(xMineR + nti * 2);
            float P0 = (kh ? acc[nti][2] : acc[nti][0]) + o.x;
            float P1 = (kh ? acc[nti][3] : acc[nti][1]) + o.y;

            int c0 = 32 * wc + 8 * nti + 2 * (l & 3);
            float2 c1v = *(const float2*)(c1S + c0);
            float2 c2v = *(const float2*)(c2S + dd * TPAD + c0);
            float2 cxv = *(const float2*)(cxS + c0);

            float v0 = fmaf(rs, P0, fmaf(nrm, c1v.x, c2v.x + cxv.x));
            float v1 = fmaf(rs, P1, fmaf(nrm, c1v.y, c2v.y + cxv.y));
            float hv0 = tanh_fast(v0);
            float hv1 = tanh_fast(v1);

            sum += hv0 + hv1;
            sq  += hv0 * hv0 + hv1 * hv1;

            sHiU[rr * 132 + (c0 >> 1)] = packh(hv0, hv1);
        }
        sum += __shfl_xor_sync(0xffffffffu, sum, 1);
        sum += __shfl_xor_sync(0xffffffffu, sum, 2);
        sq  += __shfl_xor_sync(0xffffffffu, sq, 1);
        sq  += __shfl_xor_sync(0xffffffffu, sq, 2);
        if ((l & 3) == 0) { pSum[rr * 8 + wc] = sum; pSq[rr * 8 + wc] = sq; }

        __syncthreads();                                   // bar2
    }

    // ---- output head: h_ln = (h - mu)*rs*gamma + beta, then @W_out + b_out ----
    if (tid < 160) {
        int m  = tid / 10;
        int cx = tid - m * 10;
        float4 s0 = *(const float4*)(pSum + m * 8);
        float4 s1 = *(const float4*)(pSum + m * 8 + 4);
        float4 q0 = *(const float4*)(pSq  + m * 8);
        float4 q1 = *(const float4*)(pSq  + m * 8 + 4);
        float sm = s0.x + s0.y + s0.z + s0.w + s1.x + s1.y + s1.z + s1.w;
        float qq = q0.x + q0.y + q0.z + q0.w + q1.x + q1.y + q1.z + q1.w;
        float mu = sm * (1.0f / HDIM);
        float rs = rsqrtf(qq * (1.0f / HDIM) - mu * mu + LN_EPS);

        const __half* rh = (const __half*)sHi + m * SB;
        float a = b_out[cx];
        #pragma unroll 8
        for (int k = 0; k < HDIM; k++) {
            float h  = __half2float(rh[k]);
            float hl = (h - mu) * rs * gS[k] + btS[k];
            a = fmaf(hl, __ldg(W_out + k * 10 + cx), a);
        }
        out[(size_t)(b0 + m) * 10 + cx] = a;
    }
}

extern "C" void kernel_launch(void* const* d_in, const int* in_sizes, int n_in,
                              void* d_out, int out_size)
{
    const float* x       = (const float*)d_in[0];
    const float* W_embed = (const float*)d_in[1];
    const float* b_embed = (const float*)d_in[2];
    const float* W_up    = (const float*)d_in[3];
    const float* b_up    = (const float*)d_in[4];
    const float* gamma   = (const float*)d_in[5];
    const float* beta    = (const float*)d_in[6];
    const float* W_out   = (const float*)d_in[7];
    const float* b_out   = (const float*)d_in[8];
    float* out = (float*)d_out;

    int B = out_size / 10;          // 2048
    int T = in_sizes[0] / B;        // 512

    prep_all<<<33, 256>>>(W_up, gamma, W_embed, b_embed, b_up, beta);

    size_t smem = (size_t)10 * TPAD * 4          // c2S
                + 5 * 256 * 4                    // c1,c3,bu,g,bt
                + (size_t)2 * 8 * 32 * XSTR * 4  // xbuf
                + 2 * 128 * 4                    // pSum/pSq
                + (size_t)16 * SB * 2            // sHi
                + (size_t)16 * T                 // xiT
                + 64;
    cudaFuncSetAttribute(rnn_scan_kernel,
                         cudaFuncAttributeMaxDynamicSharedMemorySize, (int)smem);
    rnn_scan_kernel<<<B / 16, TPB, smem>>>(x, b_up, gamma, beta,
                                           W_out, b_out, out, B, T);
}

// round 15
// speedup vs baseline: 3.4666x; 1.1577x over previous
#include <cuda_runtime.h>
#include <cuda_fp16.h>

#define HDIM   256
#define TPB    512
#define SB     264        // h row stride (fp16 elems)
#define TPAD   264        // c-table row stride (f32)
#define XSTR   10         // xbuf lane stride (floats); MUST be even (float2 exchange)
#define LN_EPS 1e-5f

// gamma-folded W_update in mma B-fragment lane order, fp16, uint4-packed:
// index (kt*16 + ntp)*32 + lane -> {nt0.r0, nt0.r1, nt1.r0, nt1.r1}
__device__ uint4 gBh[16 * 16 * 32];
// c-tables: rows 0..9 = c2[d] = emb(d)@W ; row 10 = c1 = gamma@W ; row 11 = c3 = beta@W + b_up
__device__ float gCtab[12 * 256];

__device__ __forceinline__ unsigned packh(float a, float b) {
    __half2 t = __floats2half2_rn(a, b);
    return *reinterpret_cast<unsigned*>(&t);
}
// HW tanh (MUFU.TANH, sm_75+): 1 MUFU op, ~1e-4 rms err — fits the error budget
// (contractive recurrence, validated R3-R13: final err ~= per-step err, no compounding).
__device__ __forceinline__ float tanh_hw(float x) {
    float y;
    asm("tanh.approx.f32 %0, %1;" : "=f"(y) : "f"(x));
    return y;
}
__device__ __forceinline__ unsigned smem_u32(const void* p) {
    unsigned r;
    asm("{ .reg .u64 t; cvta.to.shared.u64 t, %1; cvt.u32.u64 %0, t; }" : "=r"(r) : "l"(p));
    return r;
}
__device__ __forceinline__ void ldmatrix_x4(unsigned a[4], unsigned addr) {
    asm volatile("ldmatrix.sync.aligned.m8n8.x4.shared.b16 {%0,%1,%2,%3}, [%4];"
                 : "=r"(a[0]), "=r"(a[1]), "=r"(a[2]), "=r"(a[3]) : "r"(addr));
}
__device__ __forceinline__ void mma_f16(float c[4], const unsigned a[4],
                                        unsigned b0, unsigned b1) {
    asm volatile("mma.sync.aligned.m16n8k16.row.col.f32.f16.f16.f32 "
                 "{%0,%1,%2,%3}, {%4,%5,%6,%7}, {%8,%9}, {%0,%1,%2,%3};"
                 : "+f"(c[0]), "+f"(c[1]), "+f"(c[2]), "+f"(c[3])
                 : "r"(a[0]), "r"(a[1]), "r"(a[2]), "r"(a[3]), "r"(b0), "r"(b1));
}

// ---------- single prep launch: blocks 0-31 pack W, block 32 builds c-tables ----------
__global__ void prep_all(const float* __restrict__ W,
                         const float* __restrict__ gamma,
                         const float* __restrict__ W_embed,
                         const float* __restrict__ b_embed,
                         const float* __restrict__ b_up,
                         const float* __restrict__ beta) {
    if (blockIdx.x < 32) {
        int idx = blockIdx.x * 256 + threadIdx.x;        // (kt, ntp, l): 16*16*32
        int kt  = idx >> 9;
        int ntp = (idx >> 5) & 15;
        int l   = idx & 31;
        unsigned hi[4];
        #pragma unroll
        for (int s = 0; s < 2; s++) {
            int nt = 2 * ntp + s;
            int n  = nt * 8 + (l >> 2);
            int k0 = kt * 16 + (l & 3) * 2;
            hi[s * 2 + 0] = packh(W[(k0 + 0) * HDIM + n] * gamma[k0 + 0],
                                  W[(k0 + 1) * HDIM + n] * gamma[k0 + 1]);
            hi[s * 2 + 1] = packh(W[(k0 + 8) * HDIM + n] * gamma[k0 + 8],
                                  W[(k0 + 9) * HDIM + n] * gamma[k0 + 9]);
        }
        gBh[(kt * 16 + ntp) * 32 + l] = make_uint4(hi[0], hi[1], hi[2], hi[3]);
    } else {
        __shared__ float e[10][256];
        __shared__ float gsh[256], btsh[256];
        int n = threadIdx.x;
        #pragma unroll
        for (int d = 0; d < 10; d++)
            e[d][n] = tanhf((float)d * W_embed[n] + b_embed[n]);
        gsh[n]  = gamma[n];
        btsh[n] = beta[n];
        __syncthreads();

        float acc[12];
        #pragma unroll
        for (int i = 0; i < 12; i++) acc[i] = 0.f;
        #pragma unroll 4
        for (int k = 0; k < 256; k++) {
            float wv = W[k * 256 + n];                   // coalesced
            #pragma unroll
            for (int d = 0; d < 10; d++) acc[d] = fmaf(e[d][k], wv, acc[d]);
            acc[10] = fmaf(gsh[k],  wv, acc[10]);
            acc[11] = fmaf(btsh[k], wv, acc[11]);
        }
        acc[11] += b_up[n];
        #pragma unroll
        for (int i = 0; i < 12; i++) gCtab[i * 256 + n] = acc[i];
    }
}

// ---------- main persistent scan: 1 block = 16 batch rows ----------
__global__ void __launch_bounds__(TPB, 1)
rnn_scan_kernel(const float* __restrict__ x,        // [B, T, 1]
                const float* __restrict__ b_up,     // [H]
                const float* __restrict__ gamma,    // [H]
                const float* __restrict__ beta,     // [H]
                const float* __restrict__ W_out,    // [H, 10]
                const float* __restrict__ b_out,    // [10]
                float* __restrict__ out,            // [B, 10]
                int B, int T)
{
    extern __shared__ unsigned char smem_raw[];
    float* tMain = (float*)smem_raw;                      // [10][TPAD]  c2[d]+c3
    float* tZero = tMain + 10 * TPAD;                     // [10][TPAD]  c2[d]+b_up
    float* gS    = tZero + 10 * TPAD;                     // [256] (output head)
    float* btS   = gS + 256;                              // [256]
    float* xbuf  = btS + 256;                             // [2][8][32][XSTR]
    float* pSum  = xbuf + 2 * 8 * 32 * XSTR;              // [16][8]
    float* pSq   = pSum + 128;
    unsigned short* sHi = (unsigned short*)(pSq + 128);   // [16][SB] fp16 h
    unsigned char*  xiT = (unsigned char*)(sHi + 16 * SB);// [T][16]

    const int tid = threadIdx.x;
    const int w   = tid >> 5;
    const int l   = tid & 31;
    const int wc  = w & 7;                                // cols [32wc, 32wc+32)
    const int kh  = w >> 3;                               // k half
    const int b0  = blockIdx.x * 16;

    unsigned* sHiU = (unsigned*)sHi;

    const uint4* hiP0 = gBh + ((kh * 8) * 16 + 2 * wc) * 32 + l;
    const uint4* hiP1 = hiP0 + 32;

    // ---- one-time tables ----
    for (int idx = tid; idx < 10 * HDIM; idx += TPB) {
        int d  = idx / HDIM;
        int hh = idx - d * HDIM;
        float base = gCtab[d * 256 + hh];
        tMain[d * TPAD + hh] = base + gCtab[11 * 256 + hh];
        tZero[d * TPAD + hh] = base + b_up[hh];
    }
    for (int idx = tid; idx < HDIM; idx += TPB) {
        gS[idx]  = gamma[idx];
        btS[idx] = beta[idx];
    }
    for (int idx = tid; idx < 16 * T; idx += TPB) {
        int t = idx >> 4, m = idx & 15;
        xiT[t * 16 + m] = (unsigned char)__float2int_rn(x[(size_t)(b0 + m) * T + t]);
    }
    // zero-init h (t=0 GEMM then yields exactly P=0)
    for (int idx = tid; idx < 16 * 132; idx += TPB) sHiU[idx] = 0u;

    // ---- step-invariant c1 values for this lane's 8 columns (registers) ----
    float2 c1r[4];
    #pragma unroll
    for (int nti = 0; nti < 4; nti++)
        c1r[nti] = *(const float2*)(gCtab + 10 * 256 + 32 * wc + 8 * nti + 2 * (l & 3));
    __syncthreads();

    const int rr = (l >> 2) + kh * 8;                     // lane's row after exchange

    const int rowA  = (l & 7) + 8 * ((l >> 3) & 1);
    const int colbA = 8 * (l >> 4);
    const unsigned aHiBase = smem_u32(sHi) + (unsigned)(rowA * SB + colbA) * 2u
                           + (unsigned)(kh * 8) * 32u;

    float* xA = xbuf;                                     // kh1 -> kh0 (rows 0-7)
    float* xB = xbuf + 8 * 32 * XSTR;                     // kh0 -> kh1 (rows 8-15)
    float* xMineW = (kh ? xA : xB) + (wc * 32 + l) * XSTR;
    float* xMineR = (kh ? xB : xA) + (wc * 32 + l) * XSTR;

    for (int t = 0; t < T; t++) {
        // ---------------- GEMM: P_partial = h(t-1) @ (gamma.W) over this k-half ----
        float acc[4][4];
        #pragma unroll
        for (int i = 0; i < 4; i++)
            #pragma unroll
            for (int p = 0; p < 4; p++) acc[i][p] = 0.f;

        uint4 h0[2], h1[2];
        unsigned aH[2][4];
        h0[0] = __ldg(hiP0);
        h1[0] = __ldg(hiP1);
        ldmatrix_x4(aH[0], aHiBase);

        #pragma unroll
        for (int kk = 0; kk < 8; kk++) {
            const int cur = kk & 1, nxt = cur ^ 1;
            if (kk < 7) {
                h0[nxt] = __ldg(hiP0 + (kk + 1) * 512);
                h1[nxt] = __ldg(hiP1 + (kk + 1) * 512);
                ldmatrix_x4(aH[nxt], aHiBase + (unsigned)(kk + 1) * 32u);
            }
            mma_f16(acc[0], aH[cur], h0[cur].x, h0[cur].y);
            mma_f16(acc[1], aH[cur], h0[cur].z, h0[cur].w);
            mma_f16(acc[2], aH[cur], h1[cur].x, h1[cur].y);
            mma_f16(acc[3], aH[cur], h1[cur].z, h1[cur].w);
        }

        // ---- row-split K exchange: kh0 keeps rows 0-7, kh1 rows 8-15 ----
        #pragma unroll
        for (int nti = 0; nti < 4; nti++) {
            float2 snd = kh ? make_float2(acc[nti][0], acc[nti][1])
                            : make_float2(acc[nti][2], acc[nti][3]);
            *(float2*)(xMineW + nti * 2) = snd;
        }
        __syncthreads();                                   // bar1

        // ---- epilogue: stats of h(t-1) (transient), LN-postscale, HW tanh ----
        float mu = 0.f, rs = 0.f;
        if (t) {
            float4 s0 = *(const float4*)(pSum + rr * 8);
            float4 s1 = *(const float4*)(pSum + rr * 8 + 4);
            float4 q0 = *(const float4*)(pSq  + rr * 8);
            float4 q1 = *(const float4*)(pSq  + rr * 8 + 4);
            float sm = s0.x + s0.y + s0.z + s0.w + s1.x + s1.y + s1.z + s1.w;
            float qq = q0.x + q0.y + q0.z + q0.w + q1.x + q1.y + q1.z + q1.w;
            mu = sm * (1.0f / HDIM);
            rs = rsqrtf(qq * (1.0f / HDIM) - mu * mu + LN_EPS);
        }
        const float nrm = -rs * mu;
        const float* trow = (t ? tMain : tZero) + (int)xiT[t * 16 + rr] * TPAD;

        float sum = 0.f, sq = 0.f;
        #pragma unroll
        for (int nti = 0; nti < 4; nti++) {
            float2 o = *(const float2*)(xMineR + nti * 2);
            float P0 = (kh ? acc[nti][2] : acc[nti][0]) + o.x;
            float P1 = (kh ? acc[nti][3] : acc[nti][1]) + o.y;

            int c0 = 32 * wc + 8 * nti + 2 * (l & 3);
            float2 c2v = *(const float2*)(trow + c0);

            float v0 = fmaf(rs, P0, fmaf(nrm, c1r[nti].x, c2v.x));
            float v1 = fmaf(rs, P1, fmaf(nrm, c1r[nti].y, c2v.y));
            float hv0 = tanh_hw(v0);
            float hv1 = tanh_hw(v1);

            sum += hv0 + hv1;
            sq  += hv0 * hv0 + hv1 * hv1;

            sHiU[rr * 132 + (c0 >> 1)] = packh(hv0, hv1);
        }
        sum += __shfl_xor_sync(0xffffffffu, sum, 1);
        sum += __shfl_xor_sync(0xffffffffu, sum, 2);
        sq  += __shfl_xor_sync(0xffffffffu, sq, 1);
        sq  += __shfl_xor_sync(0xffffffffu, sq, 2);
        if ((l & 3) == 0) { pSum[rr * 8 + wc] = sum; pSq[rr * 8 + wc] = sq; }

        __syncthreads();                                   // bar2
    }

    // ---- output head: h_ln = (h - mu)*rs*gamma + beta, then @W_out + b_out ----
    if (tid < 160) {
        int m  = tid / 10;
        int cx = tid - m * 10;
        float4 s0 = *(const float4*)(pSum + m * 8);
        float4 s1 = *(const float4*)(pSum + m * 8 + 4);
        float4 q0 = *(const float4*)(pSq  + m * 8);
        float4 q1 = *(const float4*)(pSq  + m * 8 + 4);
        float sm = s0.x + s0.y + s0.z + s0.w + s1.x + s1.y + s1.z + s1.w;
        float qq = q0.x + q0.y + q0.z + q0.w + q1.x + q1.y + q1.z + q1.w;
        float mu = sm * (1.0f / HDIM);
        float rs = rsqrtf(qq * (1.0f / HDIM) - mu * mu + LN_EPS);

        const __half* rh = (const __half*)sHi + m * SB;
        float a = b_out[cx];
        #pragma unroll 8
        for (int k = 0; k < HDIM; k++) {
            float h  = __half2float(rh[k]);
            float hl = (h - mu) * rs * gS[k] + btS[k];
            a = fmaf(hl, __ldg(W_out + k * 10 + cx), a);
        }
        out[(size_t)(b0 + m) * 10 + cx] = a;
    }
}

extern "C" void kernel_launch(void* const* d_in, const int* in_sizes, int n_in,
                              void* d_out, int out_size)
{
    const float* x       = (const float*)d_in[0];
    const float* W_embed = (const float*)d_in[1];
    const float* b_embed = (const float*)d_in[2];
    const float* W_up    = (const float*)d_in[3];
    const float* b_up    = (const float*)d_in[4];
    const float* gamma   = (const float*)d_in[5];
    const float* beta    = (const float*)d_in[6];
    const float* W_out   = (const float*)d_in[7];
    const float* b_out   = (const float*)d_in[8];
    float* out = (float*)d_out;

    int B = out_size / 10;          // 2048
    int T = in_sizes[0] / B;        // 512

    prep_all<<<33, 256>>>(W_up, gamma, W_embed, b_embed, b_up, beta);

    size_t smem = (size_t)2 * 10 * TPAD * 4      // tMain + tZero
                + 2 * 256 * 4                    // gS, btS
                + (size_t)2 * 8 * 32 * XSTR * 4  // xbuf
                + 2 * 128 * 4                    // pSum/pSq
                + (size_t)16 * SB * 2            // sHi
                + (size_t)16 * T                 // xiT
                + 64;
    cudaFuncSetAttribute(rnn_scan_kernel,
                         cudaFuncAttributeMaxDynamicSharedMemorySize, (int)smem);
    rnn_scan_kernel<<<B / 16, TPB, smem>>>(x, b_up, gamma, beta,
                                           W_out, b_out, out, B, T);
}

// round 16
// speedup vs baseline: 3.4695x; 1.0008x over previous
#include <cuda_runtime.h>
#include <cuda_fp16.h>

#define HDIM   256
#define TPB    512
#define SB     264        // h row stride (fp16 elems)
#define TPAD   264        // c-table row stride (f32)
#define XSTR   10         // xbuf lane stride (floats); MUST be even (float2 exchange)
#define LN_EPS 1e-5f

// gamma-folded W_update in mma B-fragment lane order, fp16, uint4-packed:
// index (kt*16 + ntp)*32 + lane -> {nt0.r0, nt0.r1, nt1.r0, nt1.r1}
__device__ uint4 gBh[16 * 16 * 32];
// c-tables: rows 0..9 = c2[d] = emb(d)@W ; row 10 = c1 = gamma@W ; row 11 = c3 = beta@W + b_up
__device__ float gCtab[12 * 256];

__device__ __forceinline__ unsigned packh(float a, float b) {
    __half2 t = __floats2half2_rn(a, b);
    return *reinterpret_cast<unsigned*>(&t);
}
// HW tanh (MUFU.TANH): 1 MUFU op, ~1e-4 rms err — validated R15 (rel_err 6.08e-4).
__device__ __forceinline__ float tanh_hw(float x) {
    float y;
    asm("tanh.approx.f32 %0, %1;" : "=f"(y) : "f"(x));
    return y;
}
__device__ __forceinline__ unsigned smem_u32(const void* p) {
    unsigned r;
    asm("{ .reg .u64 t; cvta.to.shared.u64 t, %1; cvt.u32.u64 %0, t; }" : "=r"(r) : "l"(p));
    return r;
}
__device__ __forceinline__ void ldmatrix_x4(unsigned a[4], unsigned addr) {
    asm volatile("ldmatrix.sync.aligned.m8n8.x4.shared.b16 {%0,%1,%2,%3}, [%4];"
                 : "=r"(a[0]), "=r"(a[1]), "=r"(a[2]), "=r"(a[3]) : "r"(addr));
}
__device__ __forceinline__ void mma_f16(float c[4], const unsigned a[4],
                                        unsigned b0, unsigned b1) {
    asm volatile("mma.sync.aligned.m16n8k16.row.col.f32.f16.f16.f32 "
                 "{%0,%1,%2,%3}, {%4,%5,%6,%7}, {%8,%9}, {%0,%1,%2,%3};"
                 : "+f"(c[0]), "+f"(c[1]), "+f"(c[2]), "+f"(c[3])
                 : "r"(a[0]), "r"(a[1]), "r"(a[2]), "r"(a[3]), "r"(b0), "r"(b1));
}

// ---------- single prep launch: blocks 0-31 pack W, block 32 builds c-tables ----------
__global__ void prep_all(const float* __restrict__ W,
                         const float* __restrict__ gamma,
                         const float* __restrict__ W_embed,
                         const float* __restrict__ b_embed,
                         const float* __restrict__ b_up,
                         const float* __restrict__ beta) {
    if (blockIdx.x < 32) {
        int idx = blockIdx.x * 256 + threadIdx.x;        // (kt, ntp, l): 16*16*32
        int kt  = idx >> 9;
        int ntp = (idx >> 5) & 15;
        int l   = idx & 31;
        unsigned hi[4];
        #pragma unroll
        for (int s = 0; s < 2; s++) {
            int nt = 2 * ntp + s;
            int n  = nt * 8 + (l >> 2);
            int k0 = kt * 16 + (l & 3) * 2;
            hi[s * 2 + 0] = packh(W[(k0 + 0) * HDIM + n] * gamma[k0 + 0],
                                  W[(k0 + 1) * HDIM + n] * gamma[k0 + 1]);
            hi[s * 2 + 1] = packh(W[(k0 + 8) * HDIM + n] * gamma[k0 + 8],
                                  W[(k0 + 9) * HDIM + n] * gamma[k0 + 9]);
        }
        gBh[(kt * 16 + ntp) * 32 + l] = make_uint4(hi[0], hi[1], hi[2], hi[3]);
    } else {
        __shared__ float e[10][256];
        __shared__ float gsh[256], btsh[256];
        int n = threadIdx.x;
        #pragma unroll
        for (int d = 0; d < 10; d++)
            e[d][n] = tanhf((float)d * W_embed[n] + b_embed[n]);
        gsh[n]  = gamma[n];
        btsh[n] = beta[n];
        __syncthreads();

        float acc[12];
        #pragma unroll
        for (int i = 0; i < 12; i++) acc[i] = 0.f;
        #pragma unroll 4
        for (int k = 0; k < 256; k++) {
            float wv = W[k * 256 + n];                   // coalesced
            #pragma unroll
            for (int d = 0; d < 10; d++) acc[d] = fmaf(e[d][k], wv, acc[d]);
            acc[10] = fmaf(gsh[k],  wv, acc[10]);
            acc[11] = fmaf(btsh[k], wv, acc[11]);
        }
        acc[11] += b_up[n];
        #pragma unroll
        for (int i = 0; i < 12; i++) gCtab[i * 256 + n] = acc[i];
    }
}

// ---------- main persistent scan: 1 block = 16 batch rows ----------
__global__ void __launch_bounds__(TPB, 1)
rnn_scan_kernel(const float* __restrict__ x,        // [B, T, 1]
                const float* __restrict__ b_up,     // [H]
                const float* __restrict__ gamma,    // [H]
                const float* __restrict__ beta,     // [H]
                const float* __restrict__ W_out,    // [H, 10]
                const float* __restrict__ b_out,    // [10]
                float* __restrict__ out,            // [B, 10]
                int B, int T)
{
    extern __shared__ unsigned char smem_raw[];
    float* tMain = (float*)smem_raw;                      // [10][TPAD]  c2[d]+c3
    float* tZero = tMain + 10 * TPAD;                     // [10][TPAD]  c2[d]+b_up
    float* gS    = tZero + 10 * TPAD;                     // [256] (output head)
    float* btS   = gS + 256;                              // [256]
    float* xbuf  = btS + 256;                             // [2][8][32][XSTR]
    float* pSum  = xbuf + 2 * 8 * 32 * XSTR;              // [16][8]
    float* pSq   = pSum + 128;
    unsigned short* sHi = (unsigned short*)(pSq + 128);   // [16][SB] fp16 h
    unsigned char*  xiT = (unsigned char*)(sHi + 16 * SB);// [T][16]

    const int tid = threadIdx.x;
    const int w   = tid >> 5;
    const int l   = tid & 31;
    const int wc  = w & 7;                                // cols [32wc, 32wc+32)
    const int kh  = w >> 3;                               // k half
    const int b0  = blockIdx.x * 16;

    unsigned* sHiU = (unsigned*)sHi;

    // ---- persistent B fragments: this warp's 4 n-tiles x 8 k-tiles = 16 uint4 = 64 regs ----
    uint4 bReg[16];
    {
        const uint4* hiP0 = gBh + ((kh * 8) * 16 + 2 * wc) * 32 + l;
        #pragma unroll
        for (int kk = 0; kk < 8; kk++) {
            bReg[2 * kk + 0] = __ldg(hiP0 + kk * 512);
            bReg[2 * kk + 1] = __ldg(hiP0 + kk * 512 + 32);
        }
    }

    // ---- one-time tables ----
    for (int idx = tid; idx < 10 * HDIM; idx += TPB) {
        int d  = idx / HDIM;
        int hh = idx - d * HDIM;
        float base = gCtab[d * 256 + hh];
        tMain[d * TPAD + hh] = base + gCtab[11 * 256 + hh];
        tZero[d * TPAD + hh] = base + b_up[hh];
    }
    for (int idx = tid; idx < HDIM; idx += TPB) {
        gS[idx]  = gamma[idx];
        btS[idx] = beta[idx];
    }
    for (int idx = tid; idx < 16 * T; idx += TPB) {
        int t = idx >> 4, m = idx & 15;
        xiT[t * 16 + m] = (unsigned char)__float2int_rn(x[(size_t)(b0 + m) * T + t]);
    }
    // zero-init h (t=0 GEMM then yields exactly P=0)
    for (int idx = tid; idx < 16 * 132; idx += TPB) sHiU[idx] = 0u;

    // ---- step-invariant c1 values for this lane's 8 columns (registers) ----
    float2 c1r[4];
    #pragma unroll
    for (int nti = 0; nti < 4; nti++)
        c1r[nti] = *(const float2*)(gCtab + 10 * 256 + 32 * wc + 8 * nti + 2 * (l & 3));
    __syncthreads();

    const int rr = (l >> 2) + kh * 8;                     // lane's row after exchange

    const int rowA  = (l & 7) + 8 * ((l >> 3) & 1);
    const int colbA = 8 * (l >> 4);
    const unsigned aHiBase = smem_u32(sHi) + (unsigned)(rowA * SB + colbA) * 2u
                           + (unsigned)(kh * 8) * 32u;

    float* xA = xbuf;                                     // kh1 -> kh0 (rows 0-7)
    float* xB = xbuf + 8 * 32 * XSTR;                     // kh0 -> kh1 (rows 8-15)
    float* xMineW = (kh ? xA : xB) + (wc * 32 + l) * XSTR;
    float* xMineR = (kh ? xB : xA) + (wc * 32 + l) * XSTR;

    for (int t = 0; t < T; t++) {
        // ---------------- GEMM: P_partial = h(t-1) @ (gamma.W), B from registers ----
        float acc[4][4];
        #pragma unroll
        for (int i = 0; i < 4; i++)
            #pragma unroll
            for (int p = 0; p < 4; p++) acc[i][p] = 0.f;

        unsigned aH[2][4];
        ldmatrix_x4(aH[0], aHiBase);

        #pragma unroll
        for (int kk = 0; kk < 8; kk++) {
            const int cur = kk & 1, nxt = cur ^ 1;
            if (kk < 7)
                ldmatrix_x4(aH[nxt], aHiBase + (unsigned)(kk + 1) * 32u);
            mma_f16(acc[0], aH[cur], bReg[2 * kk].x,     bReg[2 * kk].y);
            mma_f16(acc[1], aH[cur], bReg[2 * kk].z,     bReg[2 * kk].w);
            mma_f16(acc[2], aH[cur], bReg[2 * kk + 1].x, bReg[2 * kk + 1].y);
            mma_f16(acc[3], aH[cur], bReg[2 * kk + 1].z, bReg[2 * kk + 1].w);
        }

        // ---- row-split K exchange: kh0 keeps rows 0-7, kh1 rows 8-15 ----
        #pragma unroll
        for (int nti = 0; nti < 4; nti++) {
            float2 snd = kh ? make_float2(acc[nti][0], acc[nti][1])
                            : make_float2(acc[nti][2], acc[nti][3]);
            *(float2*)(xMineW + nti * 2) = snd;
        }
        __syncthreads();                                   // bar1

        // ---- epilogue: stats of h(t-1) (transient), LN-postscale, HW tanh ----
        float mu = 0.f, rs = 0.f;
        if (t) {
            float4 s0 = *(const float4*)(pSum + rr * 8);
            float4 s1 = *(const float4*)(pSum + rr * 8 + 4);
            float4 q0 = *(const float4*)(pSq  + rr * 8);
            float4 q1 = *(const float4*)(pSq  + rr * 8 + 4);
            float sm = s0.x + s0.y + s0.z + s0.w + s1.x + s1.y + s1.z + s1.w;
            float qq = q0.x + q0.y + q0.z + q0.w + q1.x + q1.y + q1.z + q1.w;
            mu = sm * (1.0f / HDIM);
            rs = rsqrtf(qq * (1.0f / HDIM) - mu * mu + LN_EPS);
        }
        const float nrm = -rs * mu;
        const float* trow = (t ? tMain : tZero) + (int)xiT[t * 16 + rr] * TPAD;

        float sum = 0.f, sq = 0.f;
        #pragma unroll
        for (int nti = 0; nti < 4; nti++) {
            float2 o = *(const float2*)(xMineR + nti * 2);
            float P0 = (kh ? acc[nti][2] : acc[nti][0]) + o.x;
            float P1 = (kh ? acc[nti][3] : acc[nti][1]) + o.y;

            int c0 = 32 * wc + 8 * nti + 2 * (l & 3);
            float2 c2v = *(const float2*)(trow + c0);

            float v0 = fmaf(rs, P0, fmaf(nrm, c1r[nti].x, c2v.x));
            float v1 = fmaf(rs, P1, fmaf(nrm, c1r[nti].y, c2v.y));
            float hv0 = tanh_hw(v0);
            float hv1 = tanh_hw(v1);

            sum += hv0 + hv1;
            sq  += hv0 * hv0 + hv1 * hv1;

            sHiU[rr * 132 + (c0 >> 1)] = packh(hv0, hv1);
        }
        sum += __shfl_xor_sync(0xffffffffu, sum, 1);
        sum += __shfl_xor_sync(0xffffffffu, sum, 2);
        sq  += __shfl_xor_sync(0xffffffffu, sq, 1);
        sq  += __shfl_xor_sync(0xffffffffu, sq, 2);
        if ((l & 3) == 0) { pSum[rr * 8 + wc] = sum; pSq[rr * 8 + wc] = sq; }

        __syncthreads();                                   // bar2
    }

    // ---- output head: h_ln = (h - mu)*rs*gamma + beta, then @W_out + b_out ----
    if (tid < 160) {
        int m  = tid / 10;
        int cx = tid - m * 10;
        float4 s0 = *(const float4*)(pSum + m * 8);
        float4 s1 = *(const float4*)(pSum + m * 8 + 4);
        float4 q0 = *(const float4*)(pSq  + m * 8);
        float4 q1 = *(const float4*)(pSq  + m * 8 + 4);
        float sm = s0.x + s0.y + s0.z + s0.w + s1.x + s1.y + s1.z + s1.w;
        float qq = q0.x + q0.y + q0.z + q0.w + q1.x + q1.y + q1.z + q1.w;
        float mu = sm * (1.0f / HDIM);
        float rs = rsqrtf(qq * (1.0f / HDIM) - mu * mu + LN_EPS);

        const __half* rh = (const __half*)sHi + m * SB;
        float a = b_out[cx];
        #pragma unroll 8
        for (int k = 0; k < HDIM; k++) {
            float h  = __half2float(rh[k]);
            float hl = (h - mu) * rs * gS[k] + btS[k];
            a = fmaf(hl, __ldg(W_out + k * 10 + cx), a);
        }
        out[(size_t)(b0 + m) * 10 + cx] = a;
    }
}

extern "C" void kernel_launch(void* const* d_in, const int* in_sizes, int n_in,
                              void* d_out, int out_size)
{
    const float* x       = (const float*)d_in[0];
    const float* W_embed = (const float*)d_in[1];
    const float* b_embed = (const float*)d_in[2];
    const float* W_up    = (const float*)d_in[3];
    const float* b_up    = (const float*)d_in[4];
    const float* gamma   = (const float*)d_in[5];
    const float* beta    = (const float*)d_in[6];
    const float* W_out   = (const float*)d_in[7];
    const float* b_out   = (const float*)d_in[8];
    float* out = (float*)d_out;

    int B = out_size / 10;          // 2048
    int T = in_sizes[0] / B;        // 512

    prep_all<<<33, 256>>>(W_up, gamma, W_embed, b_embed, b_up, beta);

    size_t smem = (size_t)2 * 10 * TPAD * 4      // tMain + tZero
                + 2 * 256 * 4                    // gS, btS
                + (size_t)2 * 8 * 32 * XSTR * 4  // xbuf
                + 2 * 128 * 4                    // pSum/pSq
                + (size_t)16 * SB * 2            // sHi
                + (size_t)16 * T                 // xiT
                + 64;
    cudaFuncSetAttribute(rnn_scan_kernel,
                         cudaFuncAttributeMaxDynamicSharedMemorySize, (int)smem);
    rnn_scan_kernel<<<B / 16, TPB, smem>>>(x, b_up, gamma, beta,
                                           W_out, b_out, out, B, T);
}